// round 1
// baseline (speedup 1.0000x reference)
#include <cuda_runtime.h>
#include <cstdint>

#define NBINS   16384
#define MAXC    4096
#define TOPK    750
#define CONF_T  0.02f
#define NMS_T   0.4f
#define MASKW   24          // ceil(750/32)
#define SCALE_F 3200.0f

__device__ unsigned int       g_hist[NBINS];
__device__ unsigned int       g_cnt;
__device__ int                g_cutbin;
__device__ unsigned long long g_cand[MAXC];
__device__ unsigned int       g_mask[TOPK * MASKW];

__device__ __forceinline__ int bin_of(unsigned int bits) {
    // scores in (0.02, 1): bits in (0x3CA3D70A, 0x3F800000). Monotonic binning.
    int b = (int)(bits >> 12) - (int)(0x3CA3D70Au >> 12);
    if (b < 0) b = 0;
    if (b > NBINS - 1) b = NBINS - 1;
    return b;
}

__global__ void hist_kernel(const float2* __restrict__ conf, int n) {
    int i = blockIdx.x * blockDim.x + threadIdx.x;
    if (i >= n) return;
    float s = conf[i].y;
    if (s > CONF_T) atomicAdd(&g_hist[bin_of(__float_as_uint(s))], 1u);
}

__global__ void select_kernel() {
    // single thread: scan from top bin; expected ~8 iterations
    unsigned int cum = 0;
    int b = NBINS - 1;
    for (; b >= 0; --b) {
        cum += g_hist[b];
        if (cum >= (unsigned)TOPK) break;
    }
    g_cutbin = (b < 0) ? 0 : b;
}

__global__ void collect_kernel(const float2* __restrict__ conf, int n) {
    int i = blockIdx.x * blockDim.x + threadIdx.x;
    if (i >= n) return;
    float s = conf[i].y;
    if (s > CONF_T) {
        unsigned int bits = __float_as_uint(s);
        if (bin_of(bits) >= g_cutbin) {
            unsigned int pos = atomicAdd(&g_cnt, 1u);
            if (pos < MAXC)
                g_cand[pos] = ((unsigned long long)bits << 32) |
                              (unsigned long long)(~(unsigned int)i);
        }
    }
}

__global__ __launch_bounds__(1024) void final_kernel(
    const float4* __restrict__ loc,     // (P,4)
    const float*  __restrict__ landms,  // (P,10)
    const float*  __restrict__ prior,   // (P,4) as floats
    float* __restrict__ out)            // [750 | 750*4 | 750*10]
{
    __shared__ unsigned long long skey[MAXC];   // 32768 B
    __shared__ float bx[TOPK * 4];              // 12000 B
    __shared__ float area[TOPK];                //  3000 B
    __shared__ unsigned char kept[TOPK];        //   750 B
    __shared__ unsigned int supp[MASKW];        //    96 B
    __shared__ int scnt;

    const int tid = threadIdx.x;
    if (tid == 0) scnt = (int)min(g_cnt, (unsigned)MAXC);
    __syncthreads();
    const int cnt = scnt;

    // load candidates, pad to MAXC with key 0 (lowest)
    for (int i = tid; i < MAXC; i += 1024)
        skey[i] = (i < cnt) ? g_cand[i] : 0ull;
    __syncthreads();

    // bitonic sort, descending: (value desc, index asc via ~index in low bits)
    for (int k = 2; k <= MAXC; k <<= 1) {
        for (int j = k >> 1; j > 0; j >>= 1) {
            for (int idx = tid; idx < MAXC; idx += 1024) {
                int ixj = idx ^ j;
                if (ixj > idx) {
                    unsigned long long a = skey[idx], b = skey[ixj];
                    bool desc = ((idx & k) == 0);
                    if (desc ? (a < b) : (a > b)) { skey[idx] = b; skey[ixj] = a; }
                }
            }
            __syncthreads();
        }
    }

    // decode top-750 boxes (FP order matches reference exactly)
    for (int t = tid; t < TOPK; t += 1024) {
        kept[t] = 0;
        float x1 = 0.f, y1 = 0.f, x2 = 0.f, y2 = 0.f, ar = 0.f;
        if (t < cnt) {
            unsigned long long key = skey[t];
            unsigned int idx = ~(unsigned int)key;
            const float4 p = ((const float4*)prior)[idx];
            const float4 l = loc[idx];
            float whx = p.z * expf(l.z * 0.2f);
            float why = p.w * expf(l.w * 0.2f);
            float cx = p.x + (l.x * 0.1f) * p.z;
            float cy = p.y + (l.y * 0.1f) * p.w;
            float ux1 = cx - whx * 0.5f;
            float uy1 = cy - why * 0.5f;
            float ux2 = ux1 + whx;
            float uy2 = uy1 + why;
            x1 = ux1 * SCALE_F; y1 = uy1 * SCALE_F;
            x2 = ux2 * SCALE_F; y2 = uy2 * SCALE_F;
            ar = (x2 - x1) * (y2 - y1);
        }
        bx[t * 4 + 0] = x1; bx[t * 4 + 1] = y1;
        bx[t * 4 + 2] = x2; bx[t * 4 + 3] = y2;
        area[t] = ar;
    }
    __syncthreads();

    // IoU suppression bitmask: bit j of word (i,wd) = (iou(i,j) > thr) && (j > i)
    const int NW = TOPK * MASKW;
    for (int w = tid; w < NW; w += 1024) {
        int i  = w / MASKW;
        int wd = w % MASKW;
        unsigned int bits = 0;
        int j0 = wd * 32;
        if (j0 + 31 > i) {
            float ax1 = bx[i * 4 + 0], ay1 = bx[i * 4 + 1];
            float ax2 = bx[i * 4 + 2], ay2 = bx[i * 4 + 3];
            float aa = area[i];
            int jbeg = (j0 > i + 1) ? j0 : (i + 1);
            int jend = (j0 + 32 < TOPK) ? (j0 + 32) : TOPK;
            for (int j = jbeg; j < jend; ++j) {
                float lt0 = fmaxf(ax1, bx[j * 4 + 0]);
                float lt1 = fmaxf(ay1, bx[j * 4 + 1]);
                float rb0 = fminf(ax2, bx[j * 4 + 2]);
                float rb1 = fminf(ay2, bx[j * 4 + 3]);
                float ww = fmaxf(rb0 - lt0, 0.f);
                float hh = fmaxf(rb1 - lt1, 0.f);
                float inter = ww * hh;
                float iou = inter / (aa + area[j] - inter);
                if (iou > NMS_T) bits |= (1u << (j - j0));
            }
        }
        g_mask[w] = bits;
    }
    __syncthreads();

    // sequential suppression scan: one warp, 24 mask words in parallel per step
    if (tid < 32) {
        if (tid < MASKW) supp[tid] = 0u;
        __syncwarp();
        for (int i = 0; i < TOPK; ++i) {
            bool alive = (i < cnt) && (((supp[i >> 5] >> (i & 31)) & 1u) == 0u);
            if (alive) {
                if (tid == 0) kept[i] = 1;
                if (tid < MASKW) supp[tid] |= g_mask[i * MASKW + tid];
            }
            __syncwarp();
        }
    }
    __syncthreads();

    // outputs: [scores 750][boxes 750*4][landms 750*10]
    for (int t = tid; t < TOPK; t += 1024) {
        float kf = kept[t] ? 1.f : 0.f;
        float sv = kept[t] ? __uint_as_float((unsigned int)(skey[t] >> 32)) : 0.f;
        out[t] = sv;
        out[TOPK + t * 4 + 0] = bx[t * 4 + 0] * kf;
        out[TOPK + t * 4 + 1] = bx[t * 4 + 1] * kf;
        out[TOPK + t * 4 + 2] = bx[t * 4 + 2] * kf;
        out[TOPK + t * 4 + 3] = bx[t * 4 + 3] * kf;
    }
    for (int e = tid; e < TOPK * 10; e += 1024) {
        int i = e / 10;
        int k = e - i * 10;
        float v = 0.f;
        if (kept[i]) {
            unsigned int idx = ~(unsigned int)skey[i];
            float lr  = landms[idx * 10 + k];
            float pc  = prior[idx * 4 + (k & 1)];
            float pwh = prior[idx * 4 + 2 + (k & 1)];
            v = (pc + (pwh * lr) * 0.1f) * SCALE_F;  // (p_wh * lm) * VAR0, ref order
        }
        out[TOPK + TOPK * 4 + e] = v;
    }
}

extern "C" void kernel_launch(void* const* d_in, const int* in_sizes, int n_in,
                              void* d_out, int out_size) {
    // inputs: 0:x (unused - only shape matters, IMG=3200), 1:loc, 2:conf, 3:landms, 4:prior_box
    const float* loc    = (const float*)d_in[1];
    const float* conf   = (const float*)d_in[2];
    const float* landms = (const float*)d_in[3];
    const float* prior  = (const float*)d_in[4];
    const int P = in_sizes[4] / 4;

    void* hptr; void* cptr;
    cudaGetSymbolAddress(&hptr, g_hist);
    cudaGetSymbolAddress(&cptr, g_cnt);
    cudaMemsetAsync(hptr, 0, NBINS * sizeof(unsigned int), 0);
    cudaMemsetAsync(cptr, 0, sizeof(unsigned int), 0);

    const int T = 256;
    const int B = (P + T - 1) / T;
    hist_kernel<<<B, T>>>((const float2*)conf, P);
    select_kernel<<<1, 1>>>();
    collect_kernel<<<B, T>>>((const float2*)conf, P);
    final_kernel<<<1, 1024>>>((const float4*)loc, landms, prior, (float*)d_out);
}

// round 2
// speedup vs baseline: 1.7385x; 1.7385x over previous
#include <cuda_runtime.h>
#include <cstdint>

#define NBINS   16384
#define MAXC    2048
#define TOPK    750
#define CONF_T  0.02f
#define NMS_T   0.4f
#define MASKW   24          // ceil(750/32)
#define SCALE_F 3200.0f

__device__ unsigned int       g_hist[NBINS];
__device__ unsigned int       g_cnt;
__device__ int                g_cutbin;
__device__ unsigned long long g_cand[MAXC];
__device__ unsigned long long g_skey[TOPK];
__device__ int                g_scnt;
__device__ float4             g_box[TOPK];
__device__ float              g_area[TOPK];
__device__ unsigned int       g_mask[TOPK * MASKW];

__device__ __forceinline__ int bin_of(unsigned int bits) {
    // scores in (0.02, 1): monotonic binning on the float bit pattern
    int b = (int)(bits >> 12) - (int)(0x3CA3D70Au >> 12);
    if (b < 0) b = 0;
    if (b > NBINS - 1) b = NBINS - 1;
    return b;
}

// ---- pass 1: histogram of scores (2 priors per thread via float4) ----
__global__ void hist_kernel(const float4* __restrict__ conf2, int n2) {
    int i = blockIdx.x * blockDim.x + threadIdx.x;
    if (i >= n2) return;
    float4 c = conf2[i];
    if (c.y > CONF_T) atomicAdd(&g_hist[bin_of(__float_as_uint(c.y))], 1u);
    if (c.w > CONF_T) atomicAdd(&g_hist[bin_of(__float_as_uint(c.w))], 1u);
}

// ---- pick cutoff bin (suffix count >= TOPK) ----
__global__ void select_kernel() {
    unsigned int cum = 0;
    int b = NBINS - 1;
    for (; b >= 0; --b) {
        cum += g_hist[b];
        if (cum >= (unsigned)TOPK) break;
    }
    g_cutbin = (b < 0) ? 0 : b;
}

// ---- pass 2: collect candidate (score,index) keys ----
__global__ void collect_kernel(const float4* __restrict__ conf2, int n2) {
    int i = blockIdx.x * blockDim.x + threadIdx.x;
    if (i >= n2) return;
    float4 c = conf2[i];
    int cut = g_cutbin;
    #pragma unroll
    for (int h = 0; h < 2; ++h) {
        float s = h ? c.w : c.y;
        unsigned int idx = 2u * (unsigned)i + h;
        if (s > CONF_T) {
            unsigned int bits = __float_as_uint(s);
            if (bin_of(bits) >= cut) {
                unsigned int pos = atomicAdd(&g_cnt, 1u);
                if (pos < MAXC)
                    g_cand[pos] = ((unsigned long long)bits << 32) |
                                  (unsigned long long)(~idx);
            }
        }
    }
}

// ---- sort 2048 candidate keys, decode top-750 boxes ----
__global__ __launch_bounds__(1024) void sort_decode_kernel(
    const float4* __restrict__ loc,
    const float4* __restrict__ prior)
{
    __shared__ unsigned long long skey[MAXC];
    const int tid = threadIdx.x;
    __shared__ int scnt;
    if (tid == 0) { scnt = (int)min(g_cnt, (unsigned)MAXC); g_scnt = (int)min(g_cnt, (unsigned)MAXC); }
    __syncthreads();
    const int cnt = scnt;

    for (int i = tid; i < MAXC; i += 1024)
        skey[i] = (i < cnt) ? g_cand[i] : 0ull;
    __syncthreads();

    // bitonic sort, descending (value desc, index asc via ~index low bits)
    for (int k = 2; k <= MAXC; k <<= 1) {
        for (int j = k >> 1; j > 0; j >>= 1) {
            for (int idx = tid; idx < MAXC; idx += 1024) {
                int ixj = idx ^ j;
                if (ixj > idx) {
                    unsigned long long a = skey[idx], b = skey[ixj];
                    bool desc = ((idx & k) == 0);
                    if (desc ? (a < b) : (a > b)) { skey[idx] = b; skey[ixj] = a; }
                }
            }
            __syncthreads();
        }
    }

    // decode top-750 (FP op order matches reference)
    for (int t = tid; t < TOPK; t += 1024) {
        unsigned long long key = (t < cnt) ? skey[t] : 0ull;
        g_skey[t] = key;
        float4 b4 = make_float4(0.f, 0.f, 0.f, 0.f);
        float ar = 0.f;
        if (t < cnt) {
            unsigned int idx = ~(unsigned int)key;
            const float4 p = prior[idx];
            const float4 l = loc[idx];
            float whx = p.z * expf(l.z * 0.2f);
            float why = p.w * expf(l.w * 0.2f);
            float cx = p.x + (l.x * 0.1f) * p.z;
            float cy = p.y + (l.y * 0.1f) * p.w;
            float ux1 = cx - whx * 0.5f;
            float uy1 = cy - why * 0.5f;
            b4.x = ux1 * SCALE_F;
            b4.y = uy1 * SCALE_F;
            b4.z = (ux1 + whx) * SCALE_F;
            b4.w = (uy1 + why) * SCALE_F;
            ar = (b4.z - b4.x) * (b4.w - b4.y);
        }
        g_box[t] = b4;
        g_area[t] = ar;
    }
}

// ---- IoU suppression bitmask, grid-parallel (8 rows per 256-thread block) ----
__global__ __launch_bounds__(256) void mask_kernel() {
    __shared__ float4 sbox[TOPK];
    __shared__ float  sarea[TOPK];
    const int tid = threadIdx.x;
    for (int t = tid; t < TOPK; t += 256) {
        sbox[t] = g_box[t];
        sarea[t] = g_area[t];
    }
    __syncthreads();

    const int row  = blockIdx.x * 8 + (tid >> 5);
    const int lane = tid & 31;
    if (row >= TOPK || lane >= MASKW) return;

    const float4 bi = sbox[row];
    const float  aa = sarea[row];
    unsigned int bits = 0;
    const int j0 = lane * 32;
    int jbeg = (j0 > row + 1) ? j0 : (row + 1);
    int jend = (j0 + 32 < TOPK) ? (j0 + 32) : TOPK;
    for (int j = jbeg; j < jend; ++j) {
        float4 bj = sbox[j];
        float lt0 = fmaxf(bi.x, bj.x);
        float lt1 = fmaxf(bi.y, bj.y);
        float rb0 = fminf(bi.z, bj.z);
        float rb1 = fminf(bi.w, bj.w);
        float ww = fmaxf(rb0 - lt0, 0.f);
        float hh = fmaxf(rb1 - lt1, 0.f);
        float inter = ww * hh;
        float iou = inter / (aa + sarea[j] - inter);
        if (iou > NMS_T) bits |= (1u << (j - j0));
    }
    g_mask[row * MASKW + lane] = bits;
}

// ---- sequential suppression scan (warp 0, register state) + outputs ----
__global__ __launch_bounds__(1024) void scan_out_kernel(
    const float* __restrict__ landms,
    const float* __restrict__ prior,
    float* __restrict__ out)
{
    __shared__ unsigned int skept[MASKW];
    const int tid = threadIdx.x;

    if (tid < 32) {
        const int lane = tid;
        const int cnt = g_scnt;
        unsigned int supp = 0, keptw = 0;
        unsigned int m_next = (lane < MASKW) ? g_mask[lane] : 0u;
        for (int i = 0; i < TOPK; ++i) {
            unsigned int m = m_next;
            if (i + 1 < TOPK)
                m_next = (lane < MASKW) ? g_mask[(i + 1) * MASKW + lane] : 0u;
            unsigned int wi = __shfl_sync(0xffffffffu, supp, i >> 5);
            bool alive = (i < cnt) && (((wi >> (i & 31)) & 1u) == 0u);
            if (alive) {
                supp |= m;
                if (lane == (i >> 5)) keptw |= (1u << (i & 31));
            }
        }
        if (lane < MASKW) skept[lane] = keptw;
    }
    __syncthreads();

    // outputs: [scores 750][boxes 750*4][landms 750*10]
    for (int t = tid; t < TOPK; t += 1024) {
        bool kp = (skept[t >> 5] >> (t & 31)) & 1u;
        float kf = kp ? 1.f : 0.f;
        unsigned long long key = g_skey[t];
        out[t] = kp ? __uint_as_float((unsigned int)(key >> 32)) : 0.f;
        float4 b4 = g_box[t];
        out[TOPK + t * 4 + 0] = b4.x * kf;
        out[TOPK + t * 4 + 1] = b4.y * kf;
        out[TOPK + t * 4 + 2] = b4.z * kf;
        out[TOPK + t * 4 + 3] = b4.w * kf;
    }
    for (int e = tid; e < TOPK * 10; e += 1024) {
        int i = e / 10;
        int k = e - i * 10;
        float v = 0.f;
        if ((skept[i >> 5] >> (i & 31)) & 1u) {
            unsigned int idx = ~(unsigned int)g_skey[i];
            float lr  = landms[idx * 10 + k];
            float pc  = prior[idx * 4 + (k & 1)];
            float pwh = prior[idx * 4 + 2 + (k & 1)];
            v = (pc + (pwh * lr) * 0.1f) * SCALE_F;
        }
        out[TOPK + TOPK * 4 + e] = v;
    }
}

extern "C" void kernel_launch(void* const* d_in, const int* in_sizes, int n_in,
                              void* d_out, int out_size) {
    // inputs: 0:x (only shape matters, IMG=3200), 1:loc, 2:conf, 3:landms, 4:prior_box
    const float* loc    = (const float*)d_in[1];
    const float* conf   = (const float*)d_in[2];
    const float* landms = (const float*)d_in[3];
    const float* prior  = (const float*)d_in[4];
    const int P  = in_sizes[4] / 4;
    const int n2 = P / 2;   // two priors per float4 of conf

    void* hptr; void* cptr;
    cudaGetSymbolAddress(&hptr, g_hist);
    cudaGetSymbolAddress(&cptr, g_cnt);
    cudaMemsetAsync(hptr, 0, NBINS * sizeof(unsigned int), 0);
    cudaMemsetAsync(cptr, 0, sizeof(unsigned int), 0);

    const int T = 256;
    const int B2 = (n2 + T - 1) / T;
    hist_kernel<<<B2, T>>>((const float4*)conf, n2);
    select_kernel<<<1, 1>>>();
    collect_kernel<<<B2, T>>>((const float4*)conf, n2);
    sort_decode_kernel<<<1, 1024>>>((const float4*)loc, (const float4*)prior);
    mask_kernel<<<(TOPK + 7) / 8, 256>>>();
    scan_out_kernel<<<1, 1024>>>(landms, prior, (float*)d_out);
}